// round 6
// baseline (speedup 1.0000x reference)
#include <cuda_runtime.h>
#include <cuda_bf16.h>
#include <math.h>

// Problem constants
#define BB   64
#define CC   2048
#define HW   196
#define MM   32
#define NC   396
#define KTOT (MM * CC)          // 65536

// kernel-1 split-K
#define KS1     8
#define CSLICE  (CC / KS1)      // 256

// kernel-3 split-K
#define KS3       64
#define KSLICE3   (KTOT / KS3)  // 1024
#define KCHUNK3   64
#define NTILE3    32
#define NT3       13            // ceil(396/32)

// -------- scratch (device globals; no runtime allocation) --------
__device__ float g_part1[KS1 * BB * MM * HW];     // 12.85 MB: [ks][b][m][hw]
__device__ float g_A    [BB * MM * HW];           //  1.6 MB : [b][m][hw]
__device__ float g_bap  [BB * KTOT];              // 16.0 MB : [b][m*2048+c]
__device__ float g_part3[KS3 * BB * NC];          //  6.5 MB : [ks][b][n]

// -------- packed f32x2 helpers (Blackwell FFMA2 path) --------
__device__ __forceinline__ unsigned long long pk2(float lo, float hi) {
    unsigned long long r;
    asm("mov.b64 %0, {%1, %2};" : "=l"(r) : "f"(lo), "f"(hi));
    return r;
}
__device__ __forceinline__ void fma2(unsigned long long& d,
                                     unsigned long long a,
                                     unsigned long long b) {
    asm("fma.rn.f32x2 %0, %1, %2, %0;" : "+l"(d) : "l"(a), "l"(b));
}
__device__ __forceinline__ float red2(unsigned long long v) {
    float lo, hi;
    asm("mov.b64 {%0, %1}, %2;" : "=f"(lo), "=f"(hi) : "l"(v));
    return lo + hi;
}

// ============================================================================
// Kernel 1 (frozen — measured good): partial attention logits.
// grid (BB, KS1), block 224 (thread = hw, 196 active).
// ============================================================================
__global__ __launch_bounds__(224) void k1_logits(const float* __restrict__ x,
                                                 const float* __restrict__ Wa) {
    __shared__ float ws[16 * 16 * 4];

    const int b  = blockIdx.x;
    const int ks = blockIdx.y;
    const int t  = threadIdx.x;
    const int hw = t;

    unsigned long long acc[32];
#pragma unroll
    for (int m = 0; m < 32; ++m) acc[m] = 0ull;

    const float* xb = x + (size_t)b * CC * HW;

    for (int cc = 0; cc < CSLICE; cc += 32) {
        const int c0 = ks * CSLICE + cc;
        __syncthreads();
        for (int idx = t; idx < 512; idx += 224) {
            const int m  = idx >> 4;
            const int j2 = idx & 15;
            const float2 w = *(const float2*)(Wa + (size_t)m * CC + c0 + 2 * j2);
            float* dst = ws + (j2 * 16 + (m >> 1)) * 4 + (m & 1) * 2;
            dst[0] = w.x; dst[1] = w.y;
        }
        __syncthreads();

        if (hw < HW) {
            const ulonglong2* wsu = (const ulonglong2*)ws;
#pragma unroll
            for (int j2 = 0; j2 < 16; ++j2) {
                const float* xp = xb + (size_t)(c0 + 2 * j2) * HW + hw;
                const unsigned long long xv = pk2(xp[0], xp[HW]);
#pragma unroll
                for (int m2 = 0; m2 < 16; ++m2) {
                    const ulonglong2 w = wsu[j2 * 16 + m2];
                    fma2(acc[2 * m2],     xv, w.x);
                    fma2(acc[2 * m2 + 1], xv, w.y);
                }
            }
        }
    }

    if (hw < HW) {
        const size_t base = ((size_t)ks * BB + b) * (MM * HW) + hw;
#pragma unroll
        for (int m = 0; m < 32; ++m)
            g_part1[base + (size_t)m * HW] = red2(acc[m]);
    }
}

// ============================================================================
// Kernel 1b: reduce split-K partials, add bias, sigmoid -> g_A.
// ============================================================================
__global__ __launch_bounds__(256) void k1b_sigmoid(const float* __restrict__ ba) {
    const int i = blockIdx.x * 256 + threadIdx.x;
    const int m = (i / HW) & (MM - 1);
    float z = ba[m];
#pragma unroll
    for (int s = 0; s < KS1; ++s)
        z += g_part1[(size_t)s * (BB * MM * HW) + i];
    g_A[i] = 1.0f / (1.0f + expf(-z));
}

// ============================================================================
// Kernel 2 (frozen — measured good): BAP pooling.
// grid (32 c-tiles, 64 b), block 128. Thread tile: 2c x 8m, hw-packed f32x2.
// ============================================================================
__global__ __launch_bounds__(128) void k2_bap(const float* __restrict__ x) {
    extern __shared__ float sm2[];
    float* xs  = sm2;                 // [64][196]
    float* as_ = sm2 + 64 * HW;       // [32][196]

    const int b  = blockIdx.y;
    const int c0 = blockIdx.x * 64;
    const int t  = threadIdx.x;

    {
        const float4* xsrc = (const float4*)(x + ((size_t)b * CC + c0) * HW);
        float4* xd = (float4*)xs;
        for (int i = t; i < 64 * (HW / 4); i += 128) xd[i] = xsrc[i];
        const float4* asrc = (const float4*)(g_A + (size_t)b * (MM * HW));
        float4* ad = (float4*)as_;
        for (int i = t; i < 32 * (HW / 4); i += 128) ad[i] = asrc[i];
    }
    __syncthreads();

    const int cp = t & 31;    // c = c0 + cp and c0 + cp + 32
    const int g  = t >> 5;    // m base = g*8

    unsigned long long acc[2][8];
#pragma unroll
    for (int i = 0; i < 2; ++i)
#pragma unroll
        for (int j = 0; j < 8; ++j) acc[i][j] = 0ull;

    const ulonglong2* xu = (const ulonglong2*)xs;   // row stride 49 u2
    const ulonglong2* au = (const ulonglong2*)as_;

#pragma unroll 7
    for (int h4 = 0; h4 < HW / 4; ++h4) {
        const ulonglong2 xa = xu[cp * 49 + h4];
        const ulonglong2 xb = xu[(cp + 32) * 49 + h4];
#pragma unroll
        for (int mm = 0; mm < 8; ++mm) {
            const ulonglong2 a = au[(g * 8 + mm) * 49 + h4];
            fma2(acc[0][mm], xa.x, a.x);
            fma2(acc[0][mm], xa.y, a.y);
            fma2(acc[1][mm], xb.x, a.x);
            fma2(acc[1][mm], xb.y, a.y);
        }
    }

    const float inv = 1.0f / 196.0f;
#pragma unroll
    for (int i = 0; i < 2; ++i) {
        const int c = c0 + cp + i * 32;
#pragma unroll
        for (int mm = 0; mm < 8; ++mm) {
            const int m = g * 8 + mm;
            g_bap[(size_t)b * KTOT + (size_t)m * CC + c] = red2(acc[i][mm]) * inv;
        }
    }
}

// ============================================================================
// Kernel 3: classifier GEMM partials. grid (KS3, 13), block 128.
// Tile 64b x 32n -> 832 blocks (single wave, ~5.6/SM). Thread tile 4b x 4n
// (b = bg+16i, n = n0+ng+8j). Per k4: 8 LDS.128 (12 wavefronts) vs 32 fma2.
// smem 25.5 KB + ~80 regs -> 6 resident blocks (37.5% occ), fixing the
// grid-limited occ=18.6% of R5.
// ============================================================================
__global__ __launch_bounds__(128, 6) void k3_gemm(const float* __restrict__ Wc) {
    extern __shared__ float sm3[];
    float* baps = sm3;                 // [64][68]
    float* wcs  = sm3 + 64 * 68;       // [32][68]

    const int ks = blockIdx.x;
    const int n0 = blockIdx.y * NTILE3;
    const int t  = threadIdx.x;
    const int bg = t & 15;             // b = bg + 16*i
    const int ng = t >> 4;             // 0..7, n = n0 + ng + 8*j

    unsigned long long acc[4][4];
#pragma unroll
    for (int i = 0; i < 4; ++i)
#pragma unroll
        for (int j = 0; j < 4; ++j) acc[i][j] = 0ull;

    const size_t kbase0 = (size_t)ks * KSLICE3;

    for (int ch = 0; ch < KSLICE3 / KCHUNK3; ++ch) {
        const size_t kb = kbase0 + (size_t)ch * KCHUNK3;
        __syncthreads();
        {
            float4* bd = (float4*)baps;
            for (int i = t; i < 64 * 16; i += 128) {
                const int bb = i >> 4, k4 = i & 15;
                bd[bb * 17 + k4] =
                    *(const float4*)(g_bap + (size_t)bb * KTOT + kb + 4 * k4);
            }
            float4* wd = (float4*)wcs;
            for (int i = t; i < 32 * 16; i += 128) {
                const int r = i >> 4, k4 = i & 15;
                const int n = n0 + r;
                float4 v = make_float4(0.f, 0.f, 0.f, 0.f);
                if (n < NC)
                    v = *(const float4*)(Wc + (size_t)n * KTOT + kb + 4 * k4);
                wd[r * 17 + k4] = v;
            }
        }
        __syncthreads();

        const ulonglong2* bu = (const ulonglong2*)baps;  // row stride 17 u2
        const ulonglong2* wu = (const ulonglong2*)wcs;

#pragma unroll 4
        for (int k4 = 0; k4 < 16; ++k4) {
            ulonglong2 w[4];
#pragma unroll
            for (int j = 0; j < 4; ++j)
                w[j] = wu[(ng + 8 * j) * 17 + k4];
            ulonglong2 bv[4];
#pragma unroll
            for (int i = 0; i < 4; ++i)
                bv[i] = bu[(bg + 16 * i) * 17 + k4];
#pragma unroll
            for (int i = 0; i < 4; ++i)
#pragma unroll
                for (int j = 0; j < 4; ++j) {
                    fma2(acc[i][j], bv[i].x, w[j].x);
                    fma2(acc[i][j], bv[i].y, w[j].y);
                }
        }
    }

#pragma unroll
    for (int i = 0; i < 4; ++i) {
        const int b = bg + 16 * i;
#pragma unroll
        for (int j = 0; j < 4; ++j) {
            const int n = n0 + ng + 8 * j;
            if (n < NC)
                g_part3[((size_t)ks * BB + b) * NC + n] = red2(acc[i][j]);
        }
    }
}

// ============================================================================
// Kernel 3b: reduce K-split partials + bias -> out [64][396].
// ============================================================================
__global__ __launch_bounds__(256) void k3_reduce(const float* __restrict__ bc,
                                                 float* __restrict__ out) {
    const int i = blockIdx.x * 256 + threadIdx.x;   // exactly 25344 threads
    const int n = i % NC;
    float s = bc[n];
#pragma unroll
    for (int j = 0; j < KS3; ++j)
        s += g_part3[(size_t)j * (BB * NC) + i];
    out[i] = s;
}

// ============================================================================
extern "C" void kernel_launch(void* const* d_in, const int* in_sizes, int n_in,
                              void* d_out, int out_size) {
    const float* x  = (const float*)d_in[0];
    const float* Wa = (const float*)d_in[1];
    const float* ba = (const float*)d_in[2];
    const float* Wc = (const float*)d_in[3];
    const float* bc = (const float*)d_in[4];
    float* out = (float*)d_out;

    const int smem_k2 = (64 * HW + 32 * HW) * (int)sizeof(float);   // 75264 B
    const int smem_k3 = ((64 + 32) * 68) * (int)sizeof(float);      // 26112 B
    cudaFuncSetAttribute(k2_bap,  cudaFuncAttributeMaxDynamicSharedMemorySize, smem_k2);
    cudaFuncSetAttribute(k3_gemm, cudaFuncAttributeMaxDynamicSharedMemorySize, smem_k3);

    k1_logits<<<dim3(BB, KS1), 224>>>(x, Wa);
    k1b_sigmoid<<<(BB * MM * HW) / 256, 256>>>(ba);
    k2_bap<<<dim3(CC / 64, BB), 128, smem_k2>>>(x);
    k3_gemm<<<dim3(KS3, NT3), 128, smem_k3>>>(Wc);
    k3_reduce<<<(BB * NC) / 256, 256>>>(bc, out);

    (void)in_sizes; (void)n_in; (void)out_size;
}

// round 7
// speedup vs baseline: 1.3661x; 1.3661x over previous
#include <cuda_runtime.h>
#include <cuda_bf16.h>
#include <math.h>

// Problem constants
#define BB   64
#define CC   2048
#define HW   196
#define MM   32
#define NC   396
#define KTOT (MM * CC)          // 65536

// kernel-1 split-K
#define KS1     8
#define CSLICE  (CC / KS1)      // 256

// kernel-3 (tf32 tensor) split-K
#define KS3       64
#define KSLICE3   (KTOT / KS3)  // 1024 per block
#define KCH       32            // k per chunk
#define NCH       (KSLICE3 / KCH) // 32 chunks
#define NT3       7             // ceil(396/64)
#define SROW      36            // smem row stride in words (32 + 4 pad)

// -------- scratch (device globals; no runtime allocation) --------
__device__ float g_part1[KS1 * BB * MM * HW];     // [ks][b][m][hw]
__device__ float g_A    [BB * MM * HW];           // [b][m][hw]
__device__ float g_bap  [BB * KTOT];              // [b][m*2048+c]
__device__ float g_part3[KS3 * BB * NC];          // [ks][b][n]

// -------- packed f32x2 helpers (Blackwell FFMA2 path) --------
__device__ __forceinline__ unsigned long long pk2(float lo, float hi) {
    unsigned long long r;
    asm("mov.b64 %0, {%1, %2};" : "=l"(r) : "f"(lo), "f"(hi));
    return r;
}
__device__ __forceinline__ void fma2(unsigned long long& d,
                                     unsigned long long a,
                                     unsigned long long b) {
    asm("fma.rn.f32x2 %0, %1, %2, %0;" : "+l"(d) : "l"(a), "l"(b));
}
__device__ __forceinline__ float red2(unsigned long long v) {
    float lo, hi;
    asm("mov.b64 {%0, %1}, %2;" : "=f"(lo), "=f"(hi) : "l"(v));
    return lo + hi;
}

// -------- tf32 helpers --------
__device__ __forceinline__ unsigned f2tf(float f) {
    unsigned r;
    asm("cvt.rna.tf32.f32 %0, %1;" : "=r"(r) : "f"(f));
    return r;
}
__device__ __forceinline__ void mma_tf32(float* d,
                                         unsigned a0, unsigned a1,
                                         unsigned a2, unsigned a3,
                                         unsigned b0, unsigned b1) {
    asm("mma.sync.aligned.m16n8k8.row.col.f32.tf32.tf32.f32 "
        "{%0,%1,%2,%3}, {%4,%5,%6,%7}, {%8,%9}, {%0,%1,%2,%3};"
        : "+f"(d[0]), "+f"(d[1]), "+f"(d[2]), "+f"(d[3])
        : "r"(a0), "r"(a1), "r"(a2), "r"(a3), "r"(b0), "r"(b1));
}

// ============================================================================
// Kernel 1 (frozen — measured good): partial attention logits.
// ============================================================================
__global__ __launch_bounds__(224) void k1_logits(const float* __restrict__ x,
                                                 const float* __restrict__ Wa) {
    __shared__ float ws[16 * 16 * 4];

    const int b  = blockIdx.x;
    const int ks = blockIdx.y;
    const int t  = threadIdx.x;
    const int hw = t;

    unsigned long long acc[32];
#pragma unroll
    for (int m = 0; m < 32; ++m) acc[m] = 0ull;

    const float* xb = x + (size_t)b * CC * HW;

    for (int cc = 0; cc < CSLICE; cc += 32) {
        const int c0 = ks * CSLICE + cc;
        __syncthreads();
        for (int idx = t; idx < 512; idx += 224) {
            const int m  = idx >> 4;
            const int j2 = idx & 15;
            const float2 w = *(const float2*)(Wa + (size_t)m * CC + c0 + 2 * j2);
            float* dst = ws + (j2 * 16 + (m >> 1)) * 4 + (m & 1) * 2;
            dst[0] = w.x; dst[1] = w.y;
        }
        __syncthreads();

        if (hw < HW) {
            const ulonglong2* wsu = (const ulonglong2*)ws;
#pragma unroll
            for (int j2 = 0; j2 < 16; ++j2) {
                const float* xp = xb + (size_t)(c0 + 2 * j2) * HW + hw;
                const unsigned long long xv = pk2(xp[0], xp[HW]);
#pragma unroll
                for (int m2 = 0; m2 < 16; ++m2) {
                    const ulonglong2 w = wsu[j2 * 16 + m2];
                    fma2(acc[2 * m2],     xv, w.x);
                    fma2(acc[2 * m2 + 1], xv, w.y);
                }
            }
        }
    }

    if (hw < HW) {
        const size_t base = ((size_t)ks * BB + b) * (MM * HW) + hw;
#pragma unroll
        for (int m = 0; m < 32; ++m)
            g_part1[base + (size_t)m * HW] = red2(acc[m]);
    }
}

// ============================================================================
// Kernel 1b: reduce split-K partials, add bias, sigmoid -> g_A.
// ============================================================================
__global__ __launch_bounds__(256) void k1b_sigmoid(const float* __restrict__ ba) {
    const int i = blockIdx.x * 256 + threadIdx.x;
    const int m = (i / HW) & (MM - 1);
    float z = ba[m];
#pragma unroll
    for (int s = 0; s < KS1; ++s)
        z += g_part1[(size_t)s * (BB * MM * HW) + i];
    g_A[i] = 1.0f / (1.0f + expf(-z));
}

// ============================================================================
// Kernel 2 (frozen — measured good): BAP pooling.
// ============================================================================
__global__ __launch_bounds__(128) void k2_bap(const float* __restrict__ x) {
    extern __shared__ float sm2[];
    float* xs  = sm2;                 // [64][196]
    float* as_ = sm2 + 64 * HW;       // [32][196]

    const int b  = blockIdx.y;
    const int c0 = blockIdx.x * 64;
    const int t  = threadIdx.x;

    {
        const float4* xsrc = (const float4*)(x + ((size_t)b * CC + c0) * HW);
        float4* xd = (float4*)xs;
        for (int i = t; i < 64 * (HW / 4); i += 128) xd[i] = xsrc[i];
        const float4* asrc = (const float4*)(g_A + (size_t)b * (MM * HW));
        float4* ad = (float4*)as_;
        for (int i = t; i < 32 * (HW / 4); i += 128) ad[i] = asrc[i];
    }
    __syncthreads();

    const int cp = t & 31;
    const int g  = t >> 5;

    unsigned long long acc[2][8];
#pragma unroll
    for (int i = 0; i < 2; ++i)
#pragma unroll
        for (int j = 0; j < 8; ++j) acc[i][j] = 0ull;

    const ulonglong2* xu = (const ulonglong2*)xs;   // row stride 49 u2
    const ulonglong2* au = (const ulonglong2*)as_;

#pragma unroll 7
    for (int h4 = 0; h4 < HW / 4; ++h4) {
        const ulonglong2 xa = xu[cp * 49 + h4];
        const ulonglong2 xb = xu[(cp + 32) * 49 + h4];
#pragma unroll
        for (int mm = 0; mm < 8; ++mm) {
            const ulonglong2 a = au[(g * 8 + mm) * 49 + h4];
            fma2(acc[0][mm], xa.x, a.x);
            fma2(acc[0][mm], xa.y, a.y);
            fma2(acc[1][mm], xb.x, a.x);
            fma2(acc[1][mm], xb.y, a.y);
        }
    }

    const float inv = 1.0f / 196.0f;
#pragma unroll
    for (int i = 0; i < 2; ++i) {
        const int c = c0 + cp + i * 32;
#pragma unroll
        for (int mm = 0; mm < 8; ++mm) {
            const int m = g * 8 + mm;
            g_bap[(size_t)b * KTOT + (size_t)m * CC + c] = red2(acc[i][mm]) * inv;
        }
    }
}

// ============================================================================
// Kernel 3 (NEW — tf32 tensor cores): out_part[ks] = bap @ Wc^T over K slice.
// grid (KS3=64, NT3=7), block 128 (4 warps).
// Block tile 64m x 64n; warp tile 64m x 16n; mma m16n8k8 tf32.
// K slice 1024 = 32 chunks of 32, double-buffered smem + register prefetch.
// Smem rows padded to 36 words: A-frag banks = 4g+c (conflict-free),
// B-frag banks = lane id (conflict-free).
// ============================================================================
__global__ __launch_bounds__(128, 4) void k3_gemm(const float* __restrict__ Wc) {
    __shared__ unsigned bs[2][64 * SROW];   // bap tile, tf32 bits
    __shared__ unsigned wsm[2][64 * SROW];  // Wc tile,  tf32 bits

    const int ks = blockIdx.x;
    const int n0 = blockIdx.y * 64;
    const int t  = threadIdx.x;
    const int w    = t >> 5;
    const int lane = t & 31;
    const int g    = lane >> 2;   // group 0..7
    const int q    = lane & 3;    // quad  0..3

    const size_t kbase = (size_t)ks * KSLICE3;

    float d[4][2][4];
#pragma unroll
    for (int i = 0; i < 4; ++i)
#pragma unroll
        for (int j = 0; j < 2; ++j)
#pragma unroll
            for (int r = 0; r < 4; ++r) d[i][j][r] = 0.0f;

    // staging indices: 4 float4 per thread per array
    int srow[4], sk4[4];
#pragma unroll
    for (int r = 0; r < 4; ++r) {
        const int idx = t + 128 * r;
        srow[r] = idx >> 3;       // 0..63
        sk4[r]  = idx & 7;        // 0..7
    }

    float4 rb[4], rw[4];
    // prologue: load chunk 0
#pragma unroll
    for (int r = 0; r < 4; ++r) {
        rb[r] = *(const float4*)(g_bap + (size_t)srow[r] * KTOT + kbase + 4 * sk4[r]);
        const int n = n0 + srow[r];
        rw[r] = (n < NC)
            ? *(const float4*)(Wc + (size_t)n * KTOT + kbase + 4 * sk4[r])
            : make_float4(0.f, 0.f, 0.f, 0.f);
    }

    for (int ch = 0; ch < NCH; ++ch) {
        const int buf = ch & 1;
        // store current regs (with fp32->tf32 convert)
#pragma unroll
        for (int r = 0; r < 4; ++r) {
            unsigned* bd = &bs[buf][srow[r] * SROW + 4 * sk4[r]];
            bd[0] = f2tf(rb[r].x); bd[1] = f2tf(rb[r].y);
            bd[2] = f2tf(rb[r].z); bd[3] = f2tf(rb[r].w);
            unsigned* wd = &wsm[buf][srow[r] * SROW + 4 * sk4[r]];
            wd[0] = f2tf(rw[r].x); wd[1] = f2tf(rw[r].y);
            wd[2] = f2tf(rw[r].z); wd[3] = f2tf(rw[r].w);
        }
        __syncthreads();

        // prefetch next chunk into regs
        if (ch + 1 < NCH) {
            const size_t kb = kbase + (size_t)(ch + 1) * KCH;
#pragma unroll
            for (int r = 0; r < 4; ++r) {
                rb[r] = *(const float4*)(g_bap + (size_t)srow[r] * KTOT + kb + 4 * sk4[r]);
                const int n = n0 + srow[r];
                rw[r] = (n < NC)
                    ? *(const float4*)(Wc + (size_t)n * KTOT + kb + 4 * sk4[r])
                    : make_float4(0.f, 0.f, 0.f, 0.f);
            }
        }

        // compute: 4 k-steps of 8
        const unsigned* bsb = bs[buf];
        const unsigned* wsb = wsm[buf];
#pragma unroll
        for (int s = 0; s < 4; ++s) {
            const int k0 = 8 * s;
            unsigned b0[2], b1[2];
#pragma unroll
            for (int j = 0; j < 2; ++j) {
                const int n = 16 * w + 8 * j + g;
                b0[j] = wsb[n * SROW + k0 + q];
                b1[j] = wsb[n * SROW + k0 + q + 4];
            }
#pragma unroll
            for (int i = 0; i < 4; ++i) {
                const unsigned a0 = bsb[(16 * i + g)     * SROW + k0 + q];
                const unsigned a1 = bsb[(16 * i + 8 + g) * SROW + k0 + q];
                const unsigned a2 = bsb[(16 * i + g)     * SROW + k0 + q + 4];
                const unsigned a3 = bsb[(16 * i + 8 + g) * SROW + k0 + q + 4];
#pragma unroll
                for (int j = 0; j < 2; ++j)
                    mma_tf32(d[i][j], a0, a1, a2, a3, b0[j], b1[j]);
            }
        }
        __syncthreads();
    }

    // write partials: [ks][m][n], float2 per (c0,c1)/(c2,c3)
#pragma unroll
    for (int i = 0; i < 4; ++i) {
#pragma unroll
        for (int j = 0; j < 2; ++j) {
            const int n = n0 + 16 * w + 8 * j + 2 * q;
            if (n < NC) {
                const int m0 = 16 * i + g;
                float* p0 = g_part3 + ((size_t)ks * BB + m0) * NC + n;
                p0[0] = d[i][j][0];
                p0[1] = d[i][j][1];
                float* p1 = g_part3 + ((size_t)ks * BB + m0 + 8) * NC + n;
                p1[0] = d[i][j][2];
                p1[1] = d[i][j][3];
            }
        }
    }
}

// ============================================================================
// Kernel 3b: reduce K-split partials + bias -> out [64][396].
// ============================================================================
__global__ __launch_bounds__(256) void k3_reduce(const float* __restrict__ bc,
                                                 float* __restrict__ out) {
    const int i = blockIdx.x * 256 + threadIdx.x;   // exactly 25344 threads
    const int n = i % NC;
    float s = bc[n];
#pragma unroll
    for (int j = 0; j < KS3; ++j)
        s += g_part3[(size_t)j * (BB * NC) + i];
    out[i] = s;
}

// ============================================================================
extern "C" void kernel_launch(void* const* d_in, const int* in_sizes, int n_in,
                              void* d_out, int out_size) {
    const float* x  = (const float*)d_in[0];
    const float* Wa = (const float*)d_in[1];
    const float* ba = (const float*)d_in[2];
    const float* Wc = (const float*)d_in[3];
    const float* bc = (const float*)d_in[4];
    float* out = (float*)d_out;

    const int smem_k2 = (64 * HW + 32 * HW) * (int)sizeof(float);   // 75264 B
    cudaFuncSetAttribute(k2_bap, cudaFuncAttributeMaxDynamicSharedMemorySize, smem_k2);

    k1_logits<<<dim3(BB, KS1), 224>>>(x, Wa);
    k1b_sigmoid<<<(BB * MM * HW) / 256, 256>>>(ba);
    k2_bap<<<dim3(CC / 64, BB), 128, smem_k2>>>(x);
    k3_gemm<<<dim3(KS3, NT3), 128>>>(Wc);
    k3_reduce<<<(BB * NC) / 256, 256>>>(bc, out);

    (void)in_sizes; (void)n_in; (void)out_size;
}

// round 8
// speedup vs baseline: 1.8701x; 1.3689x over previous
#include <cuda_runtime.h>
#include <cuda_bf16.h>
#include <math.h>

// Problem constants
#define BB   64
#define CC   2048
#define HW   196
#define MM   32
#define NC   396
#define KTOT (MM * CC)          // 65536

// kernel-1 (tf32 tensor) split-K
#define KS1   4
#define KSL1  (CC / KS1)        // 512
#define XST   232               // xs row stride (words); 232%32=8 -> banks 8q+g
#define WST   36                // Wa row stride

// kernel-2 (tf32 tensor)
#define K2ST  200               // smem row stride; 200%32=8 -> banks 8g+q

// kernel-3 (tf32 tensor) split-K — frozen from R7 (measured 41.7us)
#define KS3       64
#define KSLICE3   (KTOT / KS3)  // 1024 per block
#define KCH       32
#define NCH       (KSLICE3 / KCH)
#define NT3       7
#define SROW      36

// -------- scratch (device globals; no runtime allocation) --------
__device__ float g_part1[KS1 * BB * MM * HW];     // [ks][b][m][hw]
__device__ float g_A    [BB * MM * HW];           // [b][m][hw]
__device__ float g_bap  [BB * KTOT];              // [b][m*2048+c]
__device__ float g_part3[KS3 * BB * NC];          // [ks][b][n]

// -------- tf32 helpers (validated in R7) --------
__device__ __forceinline__ unsigned f2tf(float f) {
    unsigned r;
    asm("cvt.rna.tf32.f32 %0, %1;" : "=r"(r) : "f"(f));
    return r;
}
__device__ __forceinline__ void mma_tf32(float* d,
                                         unsigned a0, unsigned a1,
                                         unsigned a2, unsigned a3,
                                         unsigned b0, unsigned b1) {
    asm("mma.sync.aligned.m16n8k8.row.col.f32.tf32.tf32.f32 "
        "{%0,%1,%2,%3}, {%4,%5,%6,%7}, {%8,%9}, {%0,%1,%2,%3};"
        : "+f"(d[0]), "+f"(d[1]), "+f"(d[2]), "+f"(d[3])
        : "r"(a0), "r"(a1), "r"(a2), "r"(a3), "r"(b0), "r"(b1));
}

// ============================================================================
// Kernel 1 (NEW — tf32): partial logits z[ks][b][m][hw] = Wa_slice @ x_slice.
// grid (64 b, 4 ks), block 256 (8 warps: 2 m-groups x 4 n-groups).
// Warp tile 16m x 56n. A-op = Wa[m][k] (stride 36), B-op = x[k=c][n=hw]
// (stride 232). Double-buffered, register-prefetched, per k3's recipe.
// ============================================================================
__global__ __launch_bounds__(256) void k1_logits(const float* __restrict__ x,
                                                 const float* __restrict__ Wa) {
    extern __shared__ unsigned sm1[];
    unsigned* xs  = sm1;                 // [2][32*232]
    unsigned* was = sm1 + 2 * 32 * XST;  // [2][32*36]

    const int b  = blockIdx.x;
    const int ks = blockIdx.y;
    const int t  = threadIdx.x;
    const int w    = t >> 5;
    const int lane = t & 31;
    const int g    = lane >> 2;
    const int q    = lane & 3;
    const int m0   = (w & 1) * 16;
    const int n0w  = (w >> 1) * 56;

    // zero the hw pad columns (196..231) of both x buffers once
    for (int i = t; i < 2 * 32 * 36; i += 256) {
        const int buf = i / 1152;
        const int r   = (i % 1152) / 36;
        const int c   = (i % 1152) % 36;
        xs[buf * (32 * XST) + r * XST + 196 + c] = 0;
    }

    float d[7][4];
#pragma unroll
    for (int j = 0; j < 7; ++j)
#pragma unroll
        for (int r = 0; r < 4; ++r) d[j][r] = 0.0f;

    const float* xb = x + (size_t)b * CC * HW;
    const int c_base = ks * KSL1;

    const int wrow = t >> 3, wcol4 = t & 7;   // Wa staging: 1 float4/thread

    float4 xv[7], wv;
    // prologue: chunk 0
#pragma unroll
    for (int r = 0; r < 7; ++r) {
        const int idx = t + 256 * r;
        if (idx < 1568) {
            const int row = idx / 49, col4 = idx % 49;
            xv[r] = *(const float4*)(xb + (size_t)(c_base + row) * HW + 4 * col4);
        }
    }
    wv = *(const float4*)(Wa + (size_t)wrow * CC + c_base + 4 * wcol4);

    for (int ch = 0; ch < KSL1 / 32; ++ch) {
        const int buf = ch & 1;
        unsigned* xsb = xs  + buf * (32 * XST);
        unsigned* wsb = was + buf * (32 * WST);
        // store current regs (fp32 -> tf32)
#pragma unroll
        for (int r = 0; r < 7; ++r) {
            const int idx = t + 256 * r;
            if (idx < 1568) {
                const int row = idx / 49, col4 = idx % 49;
                unsigned* dst = &xsb[row * XST + 4 * col4];
                dst[0] = f2tf(xv[r].x); dst[1] = f2tf(xv[r].y);
                dst[2] = f2tf(xv[r].z); dst[3] = f2tf(xv[r].w);
            }
        }
        {
            unsigned* dst = &wsb[wrow * WST + 4 * wcol4];
            dst[0] = f2tf(wv.x); dst[1] = f2tf(wv.y);
            dst[2] = f2tf(wv.z); dst[3] = f2tf(wv.w);
        }
        __syncthreads();

        // prefetch next chunk
        if (ch + 1 < KSL1 / 32) {
            const int cb = c_base + (ch + 1) * 32;
#pragma unroll
            for (int r = 0; r < 7; ++r) {
                const int idx = t + 256 * r;
                if (idx < 1568) {
                    const int row = idx / 49, col4 = idx % 49;
                    xv[r] = *(const float4*)(xb + (size_t)(cb + row) * HW + 4 * col4);
                }
            }
            wv = *(const float4*)(Wa + (size_t)wrow * CC + cb + 4 * wcol4);
        }

        // compute: 4 ksteps of 8
#pragma unroll
        for (int s = 0; s < 4; ++s) {
            const int k0 = 8 * s;
            const unsigned a0 = wsb[(m0 + g)     * WST + k0 + q];
            const unsigned a1 = wsb[(m0 + 8 + g) * WST + k0 + q];
            const unsigned a2 = wsb[(m0 + g)     * WST + k0 + q + 4];
            const unsigned a3 = wsb[(m0 + 8 + g) * WST + k0 + q + 4];
#pragma unroll
            for (int j = 0; j < 7; ++j) {
                const int n = n0w + 8 * j + g;
                const unsigned b0 = xsb[(k0 + q)     * XST + n];
                const unsigned b1 = xsb[(k0 + q + 4) * XST + n];
                mma_tf32(d[j], a0, a1, a2, a3, b0, b1);
            }
        }
        __syncthreads();
    }

    // store partials
    const size_t base = ((size_t)ks * BB + b) * (MM * HW);
#pragma unroll
    for (int j = 0; j < 7; ++j) {
        const int n = n0w + 8 * j + 2 * q;
        if (n < HW) {
            float* p0 = g_part1 + base + (size_t)(m0 + g) * HW + n;
            p0[0] = d[j][0]; p0[1] = d[j][1];
            float* p1 = g_part1 + base + (size_t)(m0 + 8 + g) * HW + n;
            p1[0] = d[j][2]; p1[1] = d[j][3];
        }
    }
}

// ============================================================================
// Kernel 1b: reduce 4 split-K partials, add bias, sigmoid -> g_A.
// ============================================================================
__global__ __launch_bounds__(256) void k1b_sigmoid(const float* __restrict__ ba) {
    const int i = blockIdx.x * 256 + threadIdx.x;
    const int m = (i / HW) & (MM - 1);
    float z = ba[m];
#pragma unroll
    for (int s = 0; s < KS1; ++s)
        z += g_part1[(size_t)s * (BB * MM * HW) + i];
    g_A[i] = 1.0f / (1.0f + expf(-z));
}

// ============================================================================
// Kernel 2 (NEW — tf32): bap[b][m][c] = (1/196) * A[m][:] . x[c][:].
// Perfect row.col orientation: A-op = A[m][hw] as stored, B-op = x[c][hw]
// as stored. grid (32 c-tiles, 64 b), block 128 (4 warps, 16n each).
// K padded 196 -> 200 (zeros), stride 200 -> banks 8g+q conflict-free.
// ============================================================================
__global__ __launch_bounds__(128) void k2_bap(const float* __restrict__ x) {
    extern __shared__ unsigned sm2u[];
    unsigned* as = sm2u;             // [32][200]
    unsigned* xs = sm2u + 32 * K2ST; // [64][200]

    const int b  = blockIdx.y;
    const int c0 = blockIdx.x * 64;
    const int t  = threadIdx.x;
    const int w    = t >> 5;
    const int lane = t & 31;
    const int g    = lane >> 2;
    const int q    = lane & 3;
    const int n0w  = w * 16;

    // stage A tile [32][196]
    {
        const float* asrc = g_A + (size_t)b * (MM * HW);
        for (int i = t; i < 32 * 49; i += 128) {
            const int row = i / 49, col4 = i % 49;
            const float4 v = *(const float4*)(asrc + (size_t)row * HW + 4 * col4);
            unsigned* dst = &as[row * K2ST + 4 * col4];
            dst[0] = f2tf(v.x); dst[1] = f2tf(v.y);
            dst[2] = f2tf(v.z); dst[3] = f2tf(v.w);
        }
    }
    // stage x tile [64][196]
    {
        const float* xsrc = x + ((size_t)b * CC + c0) * HW;
        for (int i = t; i < 64 * 49; i += 128) {
            const int row = i / 49, col4 = i % 49;
            const float4 v = *(const float4*)(xsrc + (size_t)row * HW + 4 * col4);
            unsigned* dst = &xs[row * K2ST + 4 * col4];
            dst[0] = f2tf(v.x); dst[1] = f2tf(v.y);
            dst[2] = f2tf(v.z); dst[3] = f2tf(v.w);
        }
    }
    // zero K pads 196..199
    if (t < 32 * 4) as[(t >> 2) * K2ST + 196 + (t & 3)] = 0;
    for (int i = t; i < 64 * 4; i += 128)
        xs[(i >> 2) * K2ST + 196 + (i & 3)] = 0;
    __syncthreads();

    float d[2][2][4];
#pragma unroll
    for (int mi = 0; mi < 2; ++mi)
#pragma unroll
        for (int nj = 0; nj < 2; ++nj)
#pragma unroll
            for (int r = 0; r < 4; ++r) d[mi][nj][r] = 0.0f;

#pragma unroll
    for (int s = 0; s < 25; ++s) {
        const int k0 = 8 * s;
        unsigned b0[2], b1[2];
#pragma unroll
        for (int nj = 0; nj < 2; ++nj) {
            const int n = n0w + 8 * nj + g;
            b0[nj] = xs[n * K2ST + k0 + q];
            b1[nj] = xs[n * K2ST + k0 + q + 4];
        }
#pragma unroll
        for (int mi = 0; mi < 2; ++mi) {
            const unsigned a0 = as[(16 * mi + g)     * K2ST + k0 + q];
            const unsigned a1 = as[(16 * mi + 8 + g) * K2ST + k0 + q];
            const unsigned a2 = as[(16 * mi + g)     * K2ST + k0 + q + 4];
            const unsigned a3 = as[(16 * mi + 8 + g) * K2ST + k0 + q + 4];
#pragma unroll
            for (int nj = 0; nj < 2; ++nj)
                mma_tf32(d[mi][nj], a0, a1, a2, a3, b0[nj], b1[nj]);
        }
    }

    const float inv = 1.0f / 196.0f;
#pragma unroll
    for (int mi = 0; mi < 2; ++mi) {
#pragma unroll
        for (int nj = 0; nj < 2; ++nj) {
            const int c = c0 + n0w + 8 * nj + 2 * q;
            const int m = 16 * mi + g;
            float* p0 = g_bap + (size_t)b * KTOT + (size_t)m * CC + c;
            p0[0] = d[mi][nj][0] * inv;
            p0[1] = d[mi][nj][1] * inv;
            float* p1 = g_bap + (size_t)b * KTOT + (size_t)(m + 8) * CC + c;
            p1[0] = d[mi][nj][2] * inv;
            p1[1] = d[mi][nj][3] * inv;
        }
    }
}

// ============================================================================
// Kernel 3 (frozen R7 — measured 41.7us): tf32 GEMM partials bap @ Wc^T.
// ============================================================================
__global__ __launch_bounds__(128, 4) void k3_gemm(const float* __restrict__ Wc) {
    __shared__ unsigned bs[2][64 * SROW];
    __shared__ unsigned wsm[2][64 * SROW];

    const int ks = blockIdx.x;
    const int n0 = blockIdx.y * 64;
    const int t  = threadIdx.x;
    const int w    = t >> 5;
    const int lane = t & 31;
    const int g    = lane >> 2;
    const int q    = lane & 3;

    const size_t kbase = (size_t)ks * KSLICE3;

    float d[4][2][4];
#pragma unroll
    for (int i = 0; i < 4; ++i)
#pragma unroll
        for (int j = 0; j < 2; ++j)
#pragma unroll
            for (int r = 0; r < 4; ++r) d[i][j][r] = 0.0f;

    int srow[4], sk4[4];
#pragma unroll
    for (int r = 0; r < 4; ++r) {
        const int idx = t + 128 * r;
        srow[r] = idx >> 3;
        sk4[r]  = idx & 7;
    }

    float4 rb[4], rw[4];
#pragma unroll
    for (int r = 0; r < 4; ++r) {
        rb[r] = *(const float4*)(g_bap + (size_t)srow[r] * KTOT + kbase + 4 * sk4[r]);
        const int n = n0 + srow[r];
        rw[r] = (n < NC)
            ? *(const float4*)(Wc + (size_t)n * KTOT + kbase + 4 * sk4[r])
            : make_float4(0.f, 0.f, 0.f, 0.f);
    }

    for (int ch = 0; ch < NCH; ++ch) {
        const int buf = ch & 1;
#pragma unroll
        for (int r = 0; r < 4; ++r) {
            unsigned* bd = &bs[buf][srow[r] * SROW + 4 * sk4[r]];
            bd[0] = f2tf(rb[r].x); bd[1] = f2tf(rb[r].y);
            bd[2] = f2tf(rb[r].z); bd[3] = f2tf(rb[r].w);
            unsigned* wd = &wsm[buf][srow[r] * SROW + 4 * sk4[r]];
            wd[0] = f2tf(rw[r].x); wd[1] = f2tf(rw[r].y);
            wd[2] = f2tf(rw[r].z); wd[3] = f2tf(rw[r].w);
        }
        __syncthreads();

        if (ch + 1 < NCH) {
            const size_t kb = kbase + (size_t)(ch + 1) * KCH;
#pragma unroll
            for (int r = 0; r < 4; ++r) {
                rb[r] = *(const float4*)(g_bap + (size_t)srow[r] * KTOT + kb + 4 * sk4[r]);
                const int n = n0 + srow[r];
                rw[r] = (n < NC)
                    ? *(const float4*)(Wc + (size_t)n * KTOT + kb + 4 * sk4[r])
                    : make_float4(0.f, 0.f, 0.f, 0.f);
            }
        }

        const unsigned* bsb = bs[buf];
        const unsigned* wsb = wsm[buf];
#pragma unroll
        for (int s = 0; s < 4; ++s) {
            const int k0 = 8 * s;
            unsigned b0[2], b1[2];
#pragma unroll
            for (int j = 0; j < 2; ++j) {
                const int n = 16 * w + 8 * j + g;
                b0[j] = wsb[n * SROW + k0 + q];
                b1[j] = wsb[n * SROW + k0 + q + 4];
            }
#pragma unroll
            for (int i = 0; i < 4; ++i) {
                const unsigned a0 = bsb[(16 * i + g)     * SROW + k0 + q];
                const unsigned a1 = bsb[(16 * i + 8 + g) * SROW + k0 + q];
                const unsigned a2 = bsb[(16 * i + g)     * SROW + k0 + q + 4];
                const unsigned a3 = bsb[(16 * i + 8 + g) * SROW + k0 + q + 4];
#pragma unroll
                for (int j = 0; j < 2; ++j)
                    mma_tf32(d[i][j], a0, a1, a2, a3, b0[j], b1[j]);
            }
        }
        __syncthreads();
    }

#pragma unroll
    for (int i = 0; i < 4; ++i) {
#pragma unroll
        for (int j = 0; j < 2; ++j) {
            const int n = n0 + 16 * w + 8 * j + 2 * q;
            if (n < NC) {
                const int m0 = 16 * i + g;
                float* p0 = g_part3 + ((size_t)ks * BB + m0) * NC + n;
                p0[0] = d[i][j][0];
                p0[1] = d[i][j][1];
                float* p1 = g_part3 + ((size_t)ks * BB + m0 + 8) * NC + n;
                p1[0] = d[i][j][2];
                p1[1] = d[i][j][3];
            }
        }
    }
}

// ============================================================================
// Kernel 3b: reduce K-split partials + bias -> out [64][396].
// ============================================================================
__global__ __launch_bounds__(256) void k3_reduce(const float* __restrict__ bc,
                                                 float* __restrict__ out) {
    const int i = blockIdx.x * 256 + threadIdx.x;
    const int n = i % NC;
    float s = bc[n];
#pragma unroll
    for (int j = 0; j < KS3; ++j)
        s += g_part3[(size_t)j * (BB * NC) + i];
    out[i] = s;
}

// ============================================================================
extern "C" void kernel_launch(void* const* d_in, const int* in_sizes, int n_in,
                              void* d_out, int out_size) {
    const float* x  = (const float*)d_in[0];
    const float* Wa = (const float*)d_in[1];
    const float* ba = (const float*)d_in[2];
    const float* Wc = (const float*)d_in[3];
    const float* bc = (const float*)d_in[4];
    float* out = (float*)d_out;

    const int smem_k1 = (2 * 32 * XST + 2 * 32 * WST) * 4;   // 68608 B
    const int smem_k2 = (32 + 64) * K2ST * 4;                // 76800 B
    cudaFuncSetAttribute(k1_logits, cudaFuncAttributeMaxDynamicSharedMemorySize, smem_k1);
    cudaFuncSetAttribute(k2_bap,    cudaFuncAttributeMaxDynamicSharedMemorySize, smem_k2);

    k1_logits<<<dim3(BB, KS1), 256, smem_k1>>>(x, Wa);
    k1b_sigmoid<<<(BB * MM * HW) / 256, 256>>>(ba);
    k2_bap<<<dim3(CC / 64, BB), 128, smem_k2>>>(x);
    k3_gemm<<<dim3(KS3, NT3), 128>>>(Wc);
    k3_reduce<<<(BB * NC) / 256, 256>>>(bc, out);

    (void)in_sizes; (void)n_in; (void)out_size;
}